// round 13
// baseline (speedup 1.0000x reference)
#include <cuda_runtime.h>
#include <math.h>
#include <stdint.h>

#define N_REGIONS 10
#define HIDDEN    128
#define HEADS     4
#define N_LAYERS  3
#define CHPR      7
#define TOKENS    16384
#define TW        6                          // tokens per CTA, M = 64 rows
#define NCTAS     ((TOKENS + TW - 1) / TW)   // 2731
#define NT        128                        // 4 warps

typedef unsigned long long u64;
typedef uint32_t u32;

__constant__ int c_nbr_cnt[N_REGIONS] = {5,5,5,3,3,4,3,4,2,2};
__constant__ int c_nbr[N_REGIONS][5] = {
    {0,1,2,3,4},{0,1,2,5,7},{0,1,2,3,7},{0,2,3,0,0},{0,4,5,0,0},
    {1,4,5,6,0},{5,6,9,0,0},{1,2,7,8,0},{7,8,0,0,0},{6,9,0,0,0}
};
__constant__ float c_att_src[N_LAYERS * HEADS * HIDDEN];
__constant__ float c_att_dst[N_LAYERS * HEADS * HIDDEN];

// fragment-major packed W (tf32): idx = ((l*4+h)*256 + kt*16 + nt)*32 + lane
__device__ u64 g_Wpack[N_LAYERS * HEADS * 16 * 16 * 32];

__device__ __forceinline__ float gelu_exact(float v) {
    return 0.5f * v * (1.0f + erff(v * 0.70710678118654752f));
}
__device__ __forceinline__ u32 cvt_tf32(float f) {
    u32 r; asm("cvt.rna.tf32.f32 %0, %1;" : "=r"(r) : "f"(f)); return r;
}
__device__ __forceinline__ void mma_tf32(float c[4], const u32 a[4], u32 b0, u32 b1) {
    asm volatile(
        "mma.sync.aligned.m16n8k8.row.col.f32.tf32.tf32.f32 "
        "{%0,%1,%2,%3}, {%4,%5,%6,%7}, {%8,%9}, {%0,%1,%2,%3};"
        : "+f"(c[0]), "+f"(c[1]), "+f"(c[2]), "+f"(c[3])
        : "r"(a[0]), "r"(a[1]), "r"(a[2]), "r"(a[3]), "r"(b0), "r"(b1));
}

__global__ void wpack_kernel(const float* __restrict__ W) {
    const int idx  = blockIdx.x * 256 + threadIdx.x;   // 98304 total
    const int lane = idx & 31;
    const int nt   = (idx >> 5) & 15;
    const int kt   = (idx >> 9) & 15;
    const int h    = (idx >> 13) & 3;
    const int l    = idx >> 15;
    const int tq = lane & 3, g = lane >> 2;
    const int k0 = kt * 8 + tq;
    const int e  = nt * 8 + g;
    const u32 b0 = cvt_tf32(W[((size_t)(l * 128 + k0)     * 4 + h) * 128 + e]);
    const u32 b1 = cvt_tf32(W[((size_t)(l * 128 + k0 + 4) * 4 + h) * 128 + e]);
    g_Wpack[idx] = ((u64)b1 << 32) | (u64)b0;
}

struct __align__(16) Smem {
    float nodes[64][132];        // fp32 (residual stream); rows 60..63 zero pad
    u32   nodesT[64][132];       // tf32-bit shadow of nodes (MMA1 A source)
    u32   hhT[64][132];          // per-head GEMM result, tf32 bits (MMA2 B source)
    u32   alphaT[6][10][10];     // alpha for current head, tf32 bits
    float aatt[64][8];           // [row][2h]=a_src, [2h+1]=a_dst
    float xs[TW * 70];
    float mu[64], rstd[64];
};

__global__ void __launch_bounds__(NT, 2) brain_mma_kernel(
    const float* __restrict__ x,
    const float* __restrict__ W_enc,
    const float* __restrict__ b_enc,
    const float* __restrict__ g_enc,
    const float* __restrict__ beta_enc,
    const float* __restrict__ b_gat,
    float* __restrict__ out)
{
    extern __shared__ Smem S[];
    const int t = threadIdx.x, w = t >> 5, lane = t & 31;
    const int g = lane >> 2, tq = lane & 3;
    const int tok0 = blockIdx.x * TW;
    const int r0 = w * 16 + g;          // strip rows r0, r0+8
    const int r8 = r0 + 8;

    // ---- zero pad rows (fp32 + tf32 shadow), load inputs ----
    for (int i = t; i < 4 * 132; i += NT) {
        S->nodes [60 + i / 132][i % 132] = 0.0f;
        S->nodesT[60 + i / 132][i % 132] = 0u;
    }
    for (int i = t; i < TW * 70; i += NT) {
        const int tt = i / 70, tok = tok0 + tt;
        S->xs[i] = (tok < TOKENS) ? x[(size_t)tok * 70 + (i - tt * 70)] : 0.0f;
    }
    __syncthreads();

    // ---- encoder Linear(7,128), col = t ----
    #pragma unroll 1
    for (int r = 0; r < N_REGIONS; r++) {
        float wv[CHPR];
        #pragma unroll
        for (int c = 0; c < CHPR; c++) wv[c] = W_enc[(r * CHPR + c) * 128 + t];
        const float bb = b_enc[r * 128 + t];
        #pragma unroll
        for (int tt = 0; tt < TW; tt++) {
            float acc = bb;
            #pragma unroll
            for (int c = 0; c < CHPR; c++) acc += S->xs[tt * 70 + r * CHPR + c] * wv[c];
            S->nodes[tt * 10 + r][t] = acc;
        }
    }
    __syncthreads();

    // ---- LayerNorm stats: rows 0..59 over 4 warps ----
    for (int row = w; row < 60; row += 4) {
        float v0 = S->nodes[row][lane];
        float v1 = S->nodes[row][lane + 32];
        float v2 = S->nodes[row][lane + 64];
        float v3 = S->nodes[row][lane + 96];
        float s  = v0 + v1 + v2 + v3;
        float sq = v0*v0 + v1*v1 + v2*v2 + v3*v3;
        #pragma unroll
        for (int o = 16; o > 0; o >>= 1) {
            s  += __shfl_xor_sync(0xffffffffu, s, o);
            sq += __shfl_xor_sync(0xffffffffu, sq, o);
        }
        if (lane == 0) {
            const float m = s * (1.0f / 128.0f);
            S->mu[row]   = m;
            S->rstd[row] = rsqrtf(sq * (1.0f / 128.0f) - m * m + 1e-5f);
        }
    }
    __syncthreads();

    // ---- LN affine + GELU -> nodes (+tf32 shadow) + enc output ----
    #pragma unroll 1
    for (int r = 0; r < N_REGIONS; r++) {
        const float ge = g_enc[r * 128 + t], be = beta_enc[r * 128 + t];
        #pragma unroll
        for (int tt = 0; tt < TW; tt++) {
            const int row = tt * 10 + r;
            float v = (S->nodes[row][t] - S->mu[row]) * S->rstd[row] * ge + be;
            const float gv = gelu_exact(v);
            S->nodes [row][t] = gv;
            S->nodesT[row][t] = cvt_tf32(gv);
            if (tok0 + tt < TOKENS)
                out[(size_t)TOKENS * 1280 + (size_t)(tok0 + tt) * 1280 + r * 128 + t] = gv;
        }
    }
    __syncthreads();

    // row->token mapping (for MMA2 alpha fragments & epilogue)
    const int tokr  = r0 / 10, ir  = r0 - 10 * tokr;
    const int tokr8 = r8 / 10, ir8 = r8 - 10 * tokr8;
    const int vr  = (r0 < 60) ? tokr  : -1;
    const int vr8 = (r8 < 60) ? tokr8 : -1;

    // ---- GAT layers ----
    #pragma unroll 1
    for (int l = 0; l < N_LAYERS; l++) {
        float c2[16][4];
        #pragma unroll
        for (int nt = 0; nt < 16; nt++)
            #pragma unroll
            for (int ii = 0; ii < 4; ii++) c2[nt][ii] = 0.0f;

        #pragma unroll 1
        for (int h = 0; h < HEADS; h++) {
            // ===== MMA1: hh = nodes @ W_{l,h}; dot partials fused =====
            float asl = 0.0f, adl = 0.0f, ash = 0.0f, adh = 0.0f;
            const u64* __restrict__ bp = g_Wpack + (size_t)((l * 4 + h) * 256) * 32 + lane;
            #pragma unroll 1
            for (int half = 0; half < 2; half++) {
                const u64* __restrict__ bph = bp + half * 8 * 32;
                float c1[8][4];
                #pragma unroll
                for (int nt = 0; nt < 8; nt++)
                    #pragma unroll
                    for (int ii = 0; ii < 4; ii++) c1[nt][ii] = 0.0f;

                u64 bw[8];
                #pragma unroll
                for (int nt = 0; nt < 8; nt++) bw[nt] = __ldg(bph + nt * 32);

                #pragma unroll 1
                for (int kt = 0; kt < 16; kt++) {
                    u32 a[4];
                    a[0] = S->nodesT[r0][kt * 8 + tq];
                    a[1] = S->nodesT[r8][kt * 8 + tq];
                    a[2] = S->nodesT[r0][kt * 8 + tq + 4];
                    a[3] = S->nodesT[r8][kt * 8 + tq + 4];
                    u64 bn[8];
                    const int nkt = (kt < 15) ? kt + 1 : 15;
                    #pragma unroll
                    for (int nt = 0; nt < 8; nt++)
                        bn[nt] = __ldg(bph + (nkt * 16 + nt) * 32);
                    #pragma unroll
                    for (int nt = 0; nt < 8; nt++)
                        mma_tf32(c1[nt], a, (u32)bw[nt], (u32)(bw[nt] >> 32));
                    #pragma unroll
                    for (int nt = 0; nt < 8; nt++) bw[nt] = bn[nt];
                }
                // store hh as tf32 bits + accumulate dot partials (fp32 regs)
                #pragma unroll
                for (int nt = 0; nt < 8; nt++) {
                    const int col0 = (half * 8 + nt) * 8 + 2 * tq;
                    uint2 p0, p8;
                    p0.x = cvt_tf32(c1[nt][0]); p0.y = cvt_tf32(c1[nt][1]);
                    p8.x = cvt_tf32(c1[nt][2]); p8.y = cvt_tf32(c1[nt][3]);
                    *reinterpret_cast<uint2*>(&S->hhT[r0][col0]) = p0;
                    *reinterpret_cast<uint2*>(&S->hhT[r8][col0]) = p8;
                    const float s0 = c_att_src[(l * 4 + h) * 128 + col0];
                    const float s1 = c_att_src[(l * 4 + h) * 128 + col0 + 1];
                    const float d0 = c_att_dst[(l * 4 + h) * 128 + col0];
                    const float d1 = c_att_dst[(l * 4 + h) * 128 + col0 + 1];
                    asl += c1[nt][0] * s0 + c1[nt][1] * s1;
                    adl += c1[nt][0] * d0 + c1[nt][1] * d1;
                    ash += c1[nt][2] * s0 + c1[nt][3] * s1;
                    adh += c1[nt][2] * d0 + c1[nt][3] * d1;
                }
            }
            // reduce dots over the quad
            asl += __shfl_xor_sync(0xffffffffu, asl, 1); asl += __shfl_xor_sync(0xffffffffu, asl, 2);
            adl += __shfl_xor_sync(0xffffffffu, adl, 1); adl += __shfl_xor_sync(0xffffffffu, adl, 2);
            ash += __shfl_xor_sync(0xffffffffu, ash, 1); ash += __shfl_xor_sync(0xffffffffu, ash, 2);
            adh += __shfl_xor_sync(0xffffffffu, adh, 1); adh += __shfl_xor_sync(0xffffffffu, adh, 2);
            if (tq == 0) {
                *reinterpret_cast<float2*>(&S->aatt[r0][2 * h]) = make_float2(asl, adl);
                *reinterpret_cast<float2*>(&S->aatt[r8][2 * h]) = make_float2(ash, adh);
            }
            __syncthreads();

            // ===== softmax for head h -> alphaT (tf32 bits) =====
            if (t < 60) {
                const int tok = t / 10, i = t - 10 * tok;
                const float ad = S->aatt[t][2 * h + 1];
                u32 row10[10];
                #pragma unroll
                for (int j = 0; j < 10; j++) row10[j] = 0u;
                const int cnt = c_nbr_cnt[i];
                float lg[5];
                float mx = -1e30f;
                for (int q = 0; q < cnt; q++) {
                    float v = ad + S->aatt[tok * 10 + c_nbr[i][q]][2 * h];
                    v = (v >= 0.0f) ? v : 0.2f * v;
                    lg[q] = v;
                    mx = fmaxf(mx, v);
                }
                float sum = 0.0f;
                for (int q = 0; q < cnt; q++) { lg[q] = expf(lg[q] - mx); sum += lg[q]; }
                const float inv = 1.0f / sum;
                for (int q = 0; q < cnt; q++) row10[c_nbr[i][q]] = cvt_tf32(lg[q] * inv);
                #pragma unroll
                for (int j = 0; j < 10; j++) S->alphaT[tok][i][j] = row10[j];
            }
            __syncthreads();

            // ===== MMA2: c2 += alpha_h (block-diag) @ hh_h  (operands pre-tf32) =====
            #pragma unroll 1
            for (int kt = 0; kt < 8; kt++) {
                const int k1 = kt * 8 + tq, k2 = k1 + 4;
                const int tc1 = k1 / 10, j1 = k1 - 10 * tc1;
                const int tc2 = k2 / 10, j2 = k2 - 10 * tc2;
                u32 a[4];
                a[0] = (vr  == tc1) ? S->alphaT[tc1][ir ][j1] : 0u;
                a[1] = (vr8 == tc1) ? S->alphaT[tc1][ir8][j1] : 0u;
                a[2] = (vr  == tc2) ? S->alphaT[tc2][ir ][j2] : 0u;
                a[3] = (vr8 == tc2) ? S->alphaT[tc2][ir8][j2] : 0u;
                #pragma unroll
                for (int nt = 0; nt < 16; nt++) {
                    const u32 b0 = S->hhT[kt * 8 + tq][nt * 8 + g];
                    const u32 b1 = S->hhT[kt * 8 + tq + 4][nt * 8 + g];
                    mma_tf32(c2[nt], a, b0, b1);
                }
            }
            __syncthreads();   // hhT/alphaT free for next head
        } // heads

        // ===== epilogue: mean heads + bias + GELU + residual (+tf32 shadow) =====
        {
            const float* __restrict__ bgp = b_gat + l * 128;
            #pragma unroll
            for (int nt = 0; nt < 16; nt++) {
                const int col0 = nt * 8 + 2 * tq;
                const float b0 = __ldg(bgp + col0), b1 = __ldg(bgp + col0 + 1);
                if (r0 < 60) {
                    const float n0 = gelu_exact(c2[nt][0] * 0.25f + b0) + S->nodes[r0][col0];
                    const float n1 = gelu_exact(c2[nt][1] * 0.25f + b1) + S->nodes[r0][col0 + 1];
                    *reinterpret_cast<float2*>(&S->nodes[r0][col0]) = make_float2(n0, n1);
                    uint2 sh; sh.x = cvt_tf32(n0); sh.y = cvt_tf32(n1);
                    *reinterpret_cast<uint2*>(&S->nodesT[r0][col0]) = sh;
                    if (l == N_LAYERS - 1 && tok0 + tokr < TOKENS)
                        *reinterpret_cast<float2*>(&out[(size_t)(tok0 + tokr) * 1280 + ir * 128 + col0])
                            = make_float2(n0, n1);
                }
                if (r8 < 60) {
                    const float n2 = gelu_exact(c2[nt][2] * 0.25f + b0) + S->nodes[r8][col0];
                    const float n3 = gelu_exact(c2[nt][3] * 0.25f + b1) + S->nodes[r8][col0 + 1];
                    *reinterpret_cast<float2*>(&S->nodes[r8][col0]) = make_float2(n2, n3);
                    uint2 sh; sh.x = cvt_tf32(n2); sh.y = cvt_tf32(n3);
                    *reinterpret_cast<uint2*>(&S->nodesT[r8][col0]) = sh;
                    if (l == N_LAYERS - 1 && tok0 + tokr8 < TOKENS)
                        *reinterpret_cast<float2*>(&out[(size_t)(tok0 + tokr8) * 1280 + ir8 * 128 + col0])
                            = make_float2(n2, n3);
                }
            }
        }
        __syncthreads();
    } // layers
}

extern "C" void kernel_launch(void* const* d_in, const int* in_sizes, int n_in,
                              void* d_out, int out_size) {
    (void)in_sizes; (void)n_in; (void)out_size;
    const float* x        = (const float*)d_in[0];
    const float* W_enc    = (const float*)d_in[1];
    const float* b_enc    = (const float*)d_in[2];
    const float* g_enc    = (const float*)d_in[3];
    const float* beta_enc = (const float*)d_in[4];
    const float* W_gat    = (const float*)d_in[5];
    const float* att_src  = (const float*)d_in[6];
    const float* att_dst  = (const float*)d_in[7];
    const float* b_gat    = (const float*)d_in[8];
    float* out = (float*)d_out;

    static_assert(sizeof(Smem) <= 111 * 1024, "smem too big for 2 CTAs/SM");
    cudaFuncSetAttribute(brain_mma_kernel,
                         cudaFuncAttributeMaxDynamicSharedMemorySize, (int)sizeof(Smem));

    cudaMemcpyToSymbolAsync(c_att_src, att_src, N_LAYERS * HEADS * HIDDEN * sizeof(float),
                            0, cudaMemcpyDeviceToDevice);
    cudaMemcpyToSymbolAsync(c_att_dst, att_dst, N_LAYERS * HEADS * HIDDEN * sizeof(float),
                            0, cudaMemcpyDeviceToDevice);
    wpack_kernel<<<(N_LAYERS * HEADS * 16 * 16 * 32) / 256, 256>>>(W_gat);
    brain_mma_kernel<<<NCTAS, NT, sizeof(Smem)>>>(
        x, W_enc, b_enc, g_enc, beta_enc, b_gat, out);
}

// round 14
// speedup vs baseline: 1.3123x; 1.3123x over previous
#include <cuda_runtime.h>
#include <math.h>
#include <stdint.h>

#define N_REGIONS 10
#define HIDDEN    128
#define HEADS     4
#define N_LAYERS  3
#define CHPR      7
#define TOKENS    16384
#define TW        6                          // tokens per CTA, M = 64 rows
#define NCTAS     ((TOKENS + TW - 1) / TW)   // 2731
#define NT        256                        // 8 warps: pairs split N

typedef unsigned long long u64;
typedef uint32_t u32;

__constant__ int c_nbr_cnt[N_REGIONS] = {5,5,5,3,3,4,3,4,2,2};
__constant__ int c_nbr[N_REGIONS][5] = {
    {0,1,2,3,4},{0,1,2,5,7},{0,1,2,3,7},{0,2,3,0,0},{0,4,5,0,0},
    {1,4,5,6,0},{5,6,9,0,0},{1,2,7,8,0},{7,8,0,0,0},{6,9,0,0,0}
};
__constant__ float c_att_src[N_LAYERS * HEADS * HIDDEN];
__constant__ float c_att_dst[N_LAYERS * HEADS * HIDDEN];

// fragment-major packed W (tf32): idx = ((l*4+h)*256 + kt*16 + nt)*32 + lane
__device__ u64 g_Wpack[N_LAYERS * HEADS * 16 * 16 * 32];

__device__ __forceinline__ float gelu_exact(float v) {
    return 0.5f * v * (1.0f + erff(v * 0.70710678118654752f));
}
__device__ __forceinline__ u32 cvt_tf32(float f) {
    u32 r; asm("cvt.rna.tf32.f32 %0, %1;" : "=r"(r) : "f"(f)); return r;
}
__device__ __forceinline__ void mma_tf32(float c[4], const u32 a[4], u32 b0, u32 b1) {
    asm volatile(
        "mma.sync.aligned.m16n8k8.row.col.f32.tf32.tf32.f32 "
        "{%0,%1,%2,%3}, {%4,%5,%6,%7}, {%8,%9}, {%0,%1,%2,%3};"
        : "+f"(c[0]), "+f"(c[1]), "+f"(c[2]), "+f"(c[3])
        : "r"(a[0]), "r"(a[1]), "r"(a[2]), "r"(a[3]), "r"(b0), "r"(b1));
}

__global__ void wpack_kernel(const float* __restrict__ W) {
    const int idx  = blockIdx.x * 256 + threadIdx.x;   // 98304 total
    const int lane = idx & 31;
    const int nt   = (idx >> 5) & 15;
    const int kt   = (idx >> 9) & 15;
    const int h    = (idx >> 13) & 3;
    const int l    = idx >> 15;
    const int tq = lane & 3, g = lane >> 2;
    const int k0 = kt * 8 + tq;
    const int e  = nt * 8 + g;
    const u32 b0 = cvt_tf32(W[((size_t)(l * 128 + k0)     * 4 + h) * 128 + e]);
    const u32 b1 = cvt_tf32(W[((size_t)(l * 128 + k0 + 4) * 4 + h) * 128 + e]);
    g_Wpack[idx] = ((u64)b1 << 32) | (u64)b0;
}

struct __align__(16) Smem {
    float nodes[64][132];        // fp32 residual stream; rows 60..63 zero pad
    u32   nodesT[64][132];       // tf32-bit shadow (MMA1 A source)
    u32   hhT[64][132];          // per-head GEMM result, tf32 bits (MMA2 B source)
    u32   alphaT[6][10][10];     // alpha for current head, tf32 bits
    float aatt[2][64][8];        // dot partials per n-half: [wh][row][2h+sd]
    float xs[TW * 70];
    float mu[64], rstd[64];
};

__global__ void __launch_bounds__(NT, 2) brain_mma_kernel(
    const float* __restrict__ x,
    const float* __restrict__ W_enc,
    const float* __restrict__ b_enc,
    const float* __restrict__ g_enc,
    const float* __restrict__ beta_enc,
    const float* __restrict__ b_gat,
    float* __restrict__ out)
{
    extern __shared__ Smem S[];
    const int t = threadIdx.x, w = t >> 5, lane = t & 31;
    const int g = lane >> 2, tq = lane & 3;
    const int wm = w & 3;                // strip index (shared by warp pair)
    const int wh = w >> 2;               // n-half: 0 -> ntiles 0..7, 1 -> 8..15
    const int tok0 = blockIdx.x * TW;
    const int r0 = wm * 16 + g;
    const int r8 = r0 + 8;
    const int e  = t & 127;              // feature col for elementwise phases
    const int th = t >> 7;               // token-half for elementwise phases

    // ---- zero pad rows, load inputs ----
    for (int i = t; i < 4 * 132; i += NT) {
        S->nodes [60 + i / 132][i % 132] = 0.0f;
        S->nodesT[60 + i / 132][i % 132] = 0u;
    }
    for (int i = t; i < TW * 70; i += NT) {
        const int tt = i / 70, tok = tok0 + tt;
        S->xs[i] = (tok < TOKENS) ? x[(size_t)tok * 70 + (i - tt * 70)] : 0.0f;
    }
    __syncthreads();

    // ---- encoder Linear(7,128): thread (th,e) handles tokens th, th+2, th+4 ----
    #pragma unroll 1
    for (int r = 0; r < N_REGIONS; r++) {
        float wv[CHPR];
        #pragma unroll
        for (int c = 0; c < CHPR; c++) wv[c] = W_enc[(r * CHPR + c) * 128 + e];
        const float bb = b_enc[r * 128 + e];
        #pragma unroll
        for (int q = 0; q < 3; q++) {
            const int tt = th + 2 * q;
            float acc = bb;
            #pragma unroll
            for (int c = 0; c < CHPR; c++) acc += S->xs[tt * 70 + r * CHPR + c] * wv[c];
            S->nodes[tt * 10 + r][e] = acc;
        }
    }
    __syncthreads();

    // ---- LayerNorm stats: rows 0..59 over 8 warps ----
    for (int row = w; row < 60; row += 8) {
        float v0 = S->nodes[row][lane];
        float v1 = S->nodes[row][lane + 32];
        float v2 = S->nodes[row][lane + 64];
        float v3 = S->nodes[row][lane + 96];
        float s  = v0 + v1 + v2 + v3;
        float sq = v0*v0 + v1*v1 + v2*v2 + v3*v3;
        #pragma unroll
        for (int o = 16; o > 0; o >>= 1) {
            s  += __shfl_xor_sync(0xffffffffu, s, o);
            sq += __shfl_xor_sync(0xffffffffu, sq, o);
        }
        if (lane == 0) {
            const float m = s * (1.0f / 128.0f);
            S->mu[row]   = m;
            S->rstd[row] = rsqrtf(sq * (1.0f / 128.0f) - m * m + 1e-5f);
        }
    }
    __syncthreads();

    // ---- LN affine + GELU -> nodes (+tf32 shadow) + enc output ----
    #pragma unroll 1
    for (int r = 0; r < N_REGIONS; r++) {
        const float ge = g_enc[r * 128 + e], be = beta_enc[r * 128 + e];
        #pragma unroll
        for (int q = 0; q < 3; q++) {
            const int tt = th + 2 * q;
            const int row = tt * 10 + r;
            float v = (S->nodes[row][e] - S->mu[row]) * S->rstd[row] * ge + be;
            const float gv = gelu_exact(v);
            S->nodes [row][e] = gv;
            S->nodesT[row][e] = cvt_tf32(gv);
            if (tok0 + tt < TOKENS)
                out[(size_t)TOKENS * 1280 + (size_t)(tok0 + tt) * 1280 + r * 128 + e] = gv;
        }
    }
    __syncthreads();

    // row->token mapping
    const int tokr  = r0 / 10, ir  = r0 - 10 * tokr;
    const int tokr8 = r8 / 10, ir8 = r8 - 10 * tokr8;
    const int vr  = (r0 < 60) ? tokr  : -1;
    const int vr8 = (r8 < 60) ? tokr8 : -1;

    // ---- GAT layers ----
    #pragma unroll 1
    for (int l = 0; l < N_LAYERS; l++) {
        float c2[8][4];
        #pragma unroll
        for (int nt = 0; nt < 8; nt++)
            #pragma unroll
            for (int ii = 0; ii < 4; ii++) c2[nt][ii] = 0.0f;

        #pragma unroll 1
        for (int h = 0; h < HEADS; h++) {
            // ===== MMA1: this warp's 8 n-tiles of hh = nodes @ W_{l,h} =====
            float asl = 0.0f, adl = 0.0f, ash = 0.0f, adh = 0.0f;
            {
                const u64* __restrict__ bph =
                    g_Wpack + (size_t)((l * 4 + h) * 256 + wh * 8) * 32 + lane;
                float c1[8][4];
                #pragma unroll
                for (int nt = 0; nt < 8; nt++)
                    #pragma unroll
                    for (int ii = 0; ii < 4; ii++) c1[nt][ii] = 0.0f;

                u64 bw[8];
                #pragma unroll
                for (int nt = 0; nt < 8; nt++) bw[nt] = __ldg(bph + nt * 32);

                #pragma unroll 1
                for (int kt = 0; kt < 16; kt++) {
                    u32 a[4];
                    a[0] = S->nodesT[r0][kt * 8 + tq];
                    a[1] = S->nodesT[r8][kt * 8 + tq];
                    a[2] = S->nodesT[r0][kt * 8 + tq + 4];
                    a[3] = S->nodesT[r8][kt * 8 + tq + 4];
                    u64 bn[8];
                    const int nkt = (kt < 15) ? kt + 1 : 15;
                    #pragma unroll
                    for (int nt = 0; nt < 8; nt++)
                        bn[nt] = __ldg(bph + (nkt * 16 + nt) * 32);
                    #pragma unroll
                    for (int nt = 0; nt < 8; nt++)
                        mma_tf32(c1[nt], a, (u32)bw[nt], (u32)(bw[nt] >> 32));
                    #pragma unroll
                    for (int nt = 0; nt < 8; nt++) bw[nt] = bn[nt];
                }
                // store hh (tf32 bits) + dot partials
                #pragma unroll
                for (int nt = 0; nt < 8; nt++) {
                    const int col0 = (wh * 8 + nt) * 8 + 2 * tq;
                    uint2 p0, p8;
                    p0.x = cvt_tf32(c1[nt][0]); p0.y = cvt_tf32(c1[nt][1]);
                    p8.x = cvt_tf32(c1[nt][2]); p8.y = cvt_tf32(c1[nt][3]);
                    *reinterpret_cast<uint2*>(&S->hhT[r0][col0]) = p0;
                    *reinterpret_cast<uint2*>(&S->hhT[r8][col0]) = p8;
                    const float s0 = c_att_src[(l * 4 + h) * 128 + col0];
                    const float s1 = c_att_src[(l * 4 + h) * 128 + col0 + 1];
                    const float d0 = c_att_dst[(l * 4 + h) * 128 + col0];
                    const float d1 = c_att_dst[(l * 4 + h) * 128 + col0 + 1];
                    asl += c1[nt][0] * s0 + c1[nt][1] * s1;
                    adl += c1[nt][0] * d0 + c1[nt][1] * d1;
                    ash += c1[nt][2] * s0 + c1[nt][3] * s1;
                    adh += c1[nt][2] * d0 + c1[nt][3] * d1;
                }
            }
            // quad reduce, store per-half partials
            asl += __shfl_xor_sync(0xffffffffu, asl, 1); asl += __shfl_xor_sync(0xffffffffu, asl, 2);
            adl += __shfl_xor_sync(0xffffffffu, adl, 1); adl += __shfl_xor_sync(0xffffffffu, adl, 2);
            ash += __shfl_xor_sync(0xffffffffu, ash, 1); ash += __shfl_xor_sync(0xffffffffu, ash, 2);
            adh += __shfl_xor_sync(0xffffffffu, adh, 1); adh += __shfl_xor_sync(0xffffffffu, adh, 2);
            if (tq == 0) {
                *reinterpret_cast<float2*>(&S->aatt[wh][r0][2 * h]) = make_float2(asl, adl);
                *reinterpret_cast<float2*>(&S->aatt[wh][r8][2 * h]) = make_float2(ash, adh);
            }
            __syncthreads();

            // ===== softmax for head h (sum both n-half partials) =====
            if (t < 60) {
                const int tok = t / 10, i = t - 10 * tok;
                const float ad = S->aatt[0][t][2 * h + 1] + S->aatt[1][t][2 * h + 1];
                u32 row10[10];
                #pragma unroll
                for (int j = 0; j < 10; j++) row10[j] = 0u;
                const int cnt = c_nbr_cnt[i];
                float lg[5];
                float mx = -1e30f;
                for (int q = 0; q < cnt; q++) {
                    const int jr = tok * 10 + c_nbr[i][q];
                    float v = ad + S->aatt[0][jr][2 * h] + S->aatt[1][jr][2 * h];
                    v = (v >= 0.0f) ? v : 0.2f * v;
                    lg[q] = v;
                    mx = fmaxf(mx, v);
                }
                float sum = 0.0f;
                for (int q = 0; q < cnt; q++) { lg[q] = expf(lg[q] - mx); sum += lg[q]; }
                const float inv = 1.0f / sum;
                for (int q = 0; q < cnt; q++) row10[c_nbr[i][q]] = cvt_tf32(lg[q] * inv);
                #pragma unroll
                for (int j = 0; j < 10; j++) S->alphaT[tok][i][j] = row10[j];
            }
            __syncthreads();

            // ===== MMA2: c2 += alpha_h (block-diag) @ hh_h, this warp's n-half =====
            #pragma unroll 1
            for (int kt = 0; kt < 8; kt++) {
                const int k1 = kt * 8 + tq, k2 = k1 + 4;
                const int tc1 = k1 / 10, j1 = k1 - 10 * tc1;
                const int tc2 = k2 / 10, j2 = k2 - 10 * tc2;
                u32 a[4];
                a[0] = (vr  == tc1) ? S->alphaT[tc1][ir ][j1] : 0u;
                a[1] = (vr8 == tc1) ? S->alphaT[tc1][ir8][j1] : 0u;
                a[2] = (vr  == tc2) ? S->alphaT[tc2][ir ][j2] : 0u;
                a[3] = (vr8 == tc2) ? S->alphaT[tc2][ir8][j2] : 0u;
                #pragma unroll
                for (int nt = 0; nt < 8; nt++) {
                    const int nc = (wh * 8 + nt) * 8 + g;
                    const u32 b0 = S->hhT[kt * 8 + tq][nc];
                    const u32 b1 = S->hhT[kt * 8 + tq + 4][nc];
                    mma_tf32(c2[nt], a, b0, b1);
                }
            }
            __syncthreads();   // hhT/alphaT free for next head
        } // heads

        // ===== epilogue: mean heads + bias + GELU + residual (+ shadow) =====
        {
            const float* __restrict__ bgp = b_gat + l * 128;
            #pragma unroll
            for (int nt = 0; nt < 8; nt++) {
                const int col0 = (wh * 8 + nt) * 8 + 2 * tq;
                const float b0 = __ldg(bgp + col0), b1 = __ldg(bgp + col0 + 1);
                if (r0 < 60) {
                    const float n0 = gelu_exact(c2[nt][0] * 0.25f + b0) + S->nodes[r0][col0];
                    const float n1 = gelu_exact(c2[nt][1] * 0.25f + b1) + S->nodes[r0][col0 + 1];
                    *reinterpret_cast<float2*>(&S->nodes[r0][col0]) = make_float2(n0, n1);
                    uint2 sh; sh.x = cvt_tf32(n0); sh.y = cvt_tf32(n1);
                    *reinterpret_cast<uint2*>(&S->nodesT[r0][col0]) = sh;
                    if (l == N_LAYERS - 1 && tok0 + tokr < TOKENS)
                        *reinterpret_cast<float2*>(&out[(size_t)(tok0 + tokr) * 1280 + ir * 128 + col0])
                            = make_float2(n0, n1);
                }
                if (r8 < 60) {
                    const float n2 = gelu_exact(c2[nt][2] * 0.25f + b0) + S->nodes[r8][col0];
                    const float n3 = gelu_exact(c2[nt][3] * 0.25f + b1) + S->nodes[r8][col0 + 1];
                    *reinterpret_cast<float2*>(&S->nodes[r8][col0]) = make_float2(n2, n3);
                    uint2 sh; sh.x = cvt_tf32(n2); sh.y = cvt_tf32(n3);
                    *reinterpret_cast<uint2*>(&S->nodesT[r8][col0]) = sh;
                    if (l == N_LAYERS - 1 && tok0 + tokr8 < TOKENS)
                        *reinterpret_cast<float2*>(&out[(size_t)(tok0 + tokr8) * 1280 + ir8 * 128 + col0])
                            = make_float2(n2, n3);
                }
            }
        }
        __syncthreads();
    } // layers
}

extern "C" void kernel_launch(void* const* d_in, const int* in_sizes, int n_in,
                              void* d_out, int out_size) {
    (void)in_sizes; (void)n_in; (void)out_size;
    const float* x        = (const float*)d_in[0];
    const float* W_enc    = (const float*)d_in[1];
    const float* b_enc    = (const float*)d_in[2];
    const float* g_enc    = (const float*)d_in[3];
    const float* beta_enc = (const float*)d_in[4];
    const float* W_gat    = (const float*)d_in[5];
    const float* att_src  = (const float*)d_in[6];
    const float* att_dst  = (const float*)d_in[7];
    const float* b_gat    = (const float*)d_in[8];
    float* out = (float*)d_out;

    static_assert(sizeof(Smem) <= 112 * 1024, "smem too big for 2 CTAs/SM");
    cudaFuncSetAttribute(brain_mma_kernel,
                         cudaFuncAttributeMaxDynamicSharedMemorySize, (int)sizeof(Smem));

    cudaMemcpyToSymbolAsync(c_att_src, att_src, N_LAYERS * HEADS * HIDDEN * sizeof(float),
                            0, cudaMemcpyDeviceToDevice);
    cudaMemcpyToSymbolAsync(c_att_dst, att_dst, N_LAYERS * HEADS * HIDDEN * sizeof(float),
                            0, cudaMemcpyDeviceToDevice);
    wpack_kernel<<<(N_LAYERS * HEADS * 16 * 16 * 32) / 256, 256>>>(W_gat);
    brain_mma_kernel<<<NCTAS, NT, sizeof(Smem)>>>(
        x, W_enc, b_enc, g_enc, beta_enc, b_gat, out);
}